// round 1
// baseline (speedup 1.0000x reference)
#include <cuda_runtime.h>

#define KW 7
#define PAD 3
#define H 480
#define W 640
#define NB 4
#define HW (H * W)
#define TX 32
#define TY 8
#define TILE_W (TX + 2 * PAD)   // 38
#define TILE_H (TY + 2 * PAD)   // 14
#define INV_SIGMA 50.0f          // 1 / (2*0.1^2)

__global__ __launch_bounds__(TX * TY) void bilateral_kernel(
    const float* __restrict__ I,
    const float* __restrict__ g,
    float* __restrict__ out)
{
    __shared__ float tile[NB][TILE_H][TILE_W];

    const int x0 = blockIdx.x * TX;
    const int y0 = blockIdx.y * TY;
    const int tx = threadIdx.x;
    const int ty = threadIdx.y;
    const int tid = ty * TX + tx;

    // Cooperative halo-tile load for all 4 batches (zero pad outside image).
    #pragma unroll
    for (int b = 0; b < NB; b++) {
        for (int i = tid; i < TILE_H * TILE_W; i += TX * TY) {
            const int ly = i / TILE_W;
            const int lx = i - ly * TILE_W;
            const int gy = y0 + ly - PAD;
            const int gx = x0 + lx - PAD;
            float v = 0.0f;
            if (gy >= 0 && gy < H && gx >= 0 && gx < W)
                v = I[b * HW + gy * W + gx];
            tile[b][ly][lx] = v;
        }
    }
    __syncthreads();

    const int x = x0 + tx;
    const int y = y0 + ty;

    float c[NB];
    #pragma unroll
    for (int b = 0; b < NB; b++)
        c[b] = tile[b][ty + PAD][tx + PAD];

    float num[NB], den[NB];
    #pragma unroll
    for (int b = 0; b < NB; b++) { num[b] = 0.0f; den[b] = 0.0f; }

    const float* gp = g + y * W + x;   // tap planes stride HW

    #pragma unroll
    for (int dy = 0; dy < KW; dy++) {
        #pragma unroll
        for (int dx = 0; dx < KW; dx++) {
            const float gv = __ldg(gp + (dy * KW + dx) * HW);
            #pragma unroll
            for (int b = 0; b < NB; b++) {
                const float s = tile[b][ty + dy][tx + dx];
                const float d = s - c[b];
                const float w = __expf(-INV_SIGMA * d * d) * gv;
                den[b] += w;
                num[b] = fmaf(w, s, num[b]);
            }
        }
    }

    const int oidx = y * W + x;
    #pragma unroll
    for (int b = 0; b < NB; b++)
        out[b * HW + oidx] = num[b] / den[b];
}

extern "C" void kernel_launch(void* const* d_in, const int* in_sizes, int n_in,
                              void* d_out, int out_size)
{
    const float* I = (const float*)d_in[0];
    const float* g = (const float*)d_in[1];
    float* out = (float*)d_out;

    dim3 block(TX, TY);
    dim3 grid(W / TX, H / TY);   // 20 x 60, exact
    bilateral_kernel<<<grid, block>>>(I, g, out);
}

// round 3
// speedup vs baseline: 1.1605x; 1.1605x over previous
#include <cuda_runtime.h>

#define KW 7
#define PAD 3
#define H 480
#define W 640
#define NB 4
#define HW (H * W)
#define TX 32
#define TY 8
#define TILE_W (TX + 2 * PAD)   // 38
#define TILE_H (TY + 2 * PAD)   // 14
// exponent constant: -1/(2*0.1^2) * log2(e) = -50 * 1.4426950408889634
#define NEG50_LOG2E (-72.13475204444817f)

__global__ __launch_bounds__(TX * TY) void bilateral_kernel(
    const float* __restrict__ I,
    const float* __restrict__ g,
    float* __restrict__ out)
{
    __shared__ float tile[NB][TILE_H][TILE_W];
    __shared__ float lg[KW * KW];    // log2 of spatial weights (tap-constant over H,W)

    const int x0 = blockIdx.x * TX;
    const int y0 = blockIdx.y * TY;
    const int tx = threadIdx.x;
    const int ty = threadIdx.y;
    const int tid = ty * TX + tx;

    // g is tiled over (H,W): one value per tap. Load 49 values, take log2.
    if (tid < KW * KW)
        lg[tid] = __log2f(__ldg(g + tid * HW));

    // Cooperative halo-tile load for all 4 batches (zero pad outside image).
    #pragma unroll
    for (int b = 0; b < NB; b++) {
        for (int i = tid; i < TILE_H * TILE_W; i += TX * TY) {
            const int ly = i / TILE_W;
            const int lx = i - ly * TILE_W;
            const int gy = y0 + ly - PAD;
            const int gx = x0 + lx - PAD;
            float v = 0.0f;
            if (gy >= 0 && gy < H && gx >= 0 && gx < W)
                v = I[b * HW + gy * W + gx];
            tile[b][ly][lx] = v;
        }
    }
    __syncthreads();

    float c[NB];
    #pragma unroll
    for (int b = 0; b < NB; b++)
        c[b] = tile[b][ty + PAD][tx + PAD];

    float num[NB], den[NB];
    #pragma unroll
    for (int b = 0; b < NB; b++) { num[b] = 0.0f; den[b] = 0.0f; }

    #pragma unroll
    for (int dy = 0; dy < KW; dy++) {
        #pragma unroll
        for (int dx = 0; dx < KW; dx++) {
            const float lgv = lg[dy * KW + dx];
            #pragma unroll
            for (int b = 0; b < NB; b++) {
                const float s = tile[b][ty + dy][tx + dx];
                const float d = s - c[b];
                const float d2 = d * d;
                const float w = exp2f(fmaf(NEG50_LOG2E, d2, lgv));
                den[b] += w;
                num[b] = fmaf(w, s, num[b]);
            }
        }
    }

    const int oidx = (y0 + ty) * W + (x0 + tx);
    #pragma unroll
    for (int b = 0; b < NB; b++)
        out[b * HW + oidx] = __fdividef(num[b], den[b]);
}

extern "C" void kernel_launch(void* const* d_in, const int* in_sizes, int n_in,
                              void* d_out, int out_size)
{
    const float* I = (const float*)d_in[0];
    const float* g = (const float*)d_in[1];
    float* out = (float*)d_out;

    dim3 block(TX, TY);
    dim3 grid(W / TX, H / TY);   // 20 x 60, exact
    bilateral_kernel<<<grid, block>>>(I, g, out);
}

// round 7
// speedup vs baseline: 1.3425x; 1.1568x over previous
#include <cuda_runtime.h>

#define KW 7
#define PAD 3
#define H 480
#define W 640
#define NB 4
#define HW (H * W)
#define TX 32
#define TY 8
#define TILE_W (TX + 2 * PAD)   // 38
#define TILE_H (TY + 2 * PAD)   // 14
// exponent constant: -1/(2*0.1^2) * log2(e) = -50 * log2(e)
#define NEG50_LOG2E (-72.13475204444817f)

typedef unsigned long long u64;

__device__ __forceinline__ u64 pk(float lo, float hi) {
    u64 r; asm("mov.b64 %0, {%1, %2};" : "=l"(r) : "f"(lo), "f"(hi)); return r;
}
__device__ __forceinline__ void upk(float& lo, float& hi, u64 v) {
    asm("mov.b64 {%0, %1}, %2;" : "=f"(lo), "=f"(hi) : "l"(v));
}
__device__ __forceinline__ u64 add2(u64 a, u64 b) {
    u64 r; asm("add.rn.f32x2 %0, %1, %2;" : "=l"(r) : "l"(a), "l"(b)); return r;
}
__device__ __forceinline__ u64 mul2(u64 a, u64 b) {
    u64 r; asm("mul.rn.f32x2 %0, %1, %2;" : "=l"(r) : "l"(a), "l"(b)); return r;
}
__device__ __forceinline__ u64 fma2(u64 a, u64 b, u64 c) {
    u64 r; asm("fma.rn.f32x2 %0, %1, %2, %3;" : "=l"(r) : "l"(a), "l"(b), "l"(c)); return r;
}
__device__ __forceinline__ float ex2(float x) {
    float r; asm("ex2.approx.f32 %0, %1;" : "=f"(r) : "f"(x)); return r;
}

__global__ __launch_bounds__(TX * TY) void bilateral_kernel(
    const float* __restrict__ I,
    const float* __restrict__ g,
    float* __restrict__ out)
{
    __shared__ float4 tile[TILE_H][TILE_W];   // batch-interleaved: 8512 B
    __shared__ float2 lg2s[KW * KW];          // pre-broadcast log2(g) per tap

    const int x0 = blockIdx.x * TX;
    const int y0 = blockIdx.y * TY;
    const int tx = threadIdx.x;
    const int ty = threadIdx.y;
    const int tid = ty * TX + tx;

    if (tid < KW * KW) {
        const float lv = __log2f(__ldg(g + tid * HW));
        lg2s[tid] = make_float2(lv, lv);
    }

    // Halo tile: each thread loads the 4 batch values for its pixel(s)
    // (per-batch gmem reads stay coalesced), stores one float4.
    for (int i = tid; i < TILE_H * TILE_W; i += TX * TY) {
        const int ly = i / TILE_W;
        const int lx = i - ly * TILE_W;
        const int gy = y0 + ly - PAD;
        const int gx = x0 + lx - PAD;
        float4 v = make_float4(0.f, 0.f, 0.f, 0.f);
        if (gy >= 0 && gy < H && gx >= 0 && gx < W) {
            const int base = gy * W + gx;
            v.x = I[0 * HW + base];
            v.y = I[1 * HW + base];
            v.z = I[2 * HW + base];
            v.w = I[3 * HW + base];
        }
        tile[ly][lx] = v;
    }
    __syncthreads();

    const float4 cc = tile[ty + PAD][tx + PAD];
    const u64 nc01 = pk(-cc.x, -cc.y);
    const u64 nc23 = pk(-cc.z, -cc.w);
    const u64 C2 = pk(NEG50_LOG2E, NEG50_LOG2E);

    u64 num01 = 0ull, num23 = 0ull, den01 = 0ull, den23 = 0ull;

    #pragma unroll
    for (int dy = 0; dy < KW; dy++) {
        #pragma unroll
        for (int dx = 0; dx < KW; dx++) {
            const float4 s = tile[ty + dy][tx + dx];           // LDS.128
            const u64 lgb = *reinterpret_cast<const u64*>(&lg2s[dy * KW + dx]); // LDS.64 bcast

            const u64 s01 = pk(s.x, s.y);
            const u64 s23 = pk(s.z, s.w);

            const u64 d01 = add2(s01, nc01);
            const u64 d23 = add2(s23, nc23);
            const u64 q01 = mul2(d01, d01);
            const u64 q23 = mul2(d23, d23);
            const u64 e01 = fma2(C2, q01, lgb);
            const u64 e23 = fma2(C2, q23, lgb);

            float e0, e1, e2, e3;
            upk(e0, e1, e01);
            upk(e2, e3, e23);
            const u64 w01 = pk(ex2(e0), ex2(e1));
            const u64 w23 = pk(ex2(e2), ex2(e3));

            den01 = add2(den01, w01);
            den23 = add2(den23, w23);
            num01 = fma2(w01, s01, num01);
            num23 = fma2(w23, s23, num23);
        }
    }

    float n0, n1, n2, n3, de0, de1, de2, de3;
    upk(n0, n1, num01); upk(n2, n3, num23);
    upk(de0, de1, den01); upk(de2, de3, den23);

    const int oidx = (y0 + ty) * W + (x0 + tx);
    out[0 * HW + oidx] = __fdividef(n0, de0);
    out[1 * HW + oidx] = __fdividef(n1, de1);
    out[2 * HW + oidx] = __fdividef(n2, de2);
    out[3 * HW + oidx] = __fdividef(n3, de3);
}

extern "C" void kernel_launch(void* const* d_in, const int* in_sizes, int n_in,
                              void* d_out, int out_size)
{
    const float* I = (const float*)d_in[0];
    const float* g = (const float*)d_in[1];
    float* out = (float*)d_out;

    dim3 block(TX, TY);
    dim3 grid(W / TX, H / TY);   // 20 x 60, exact
    bilateral_kernel<<<grid, block>>>(I, g, out);
}